// round 5
// baseline (speedup 1.0000x reference)
#include <cuda_runtime.h>

// Problem constants
#define NBC   6            // batch*channel = 2*3
#define NZ    128
#define NY    128
#define NX    128
#define VOL   (NZ*NY*NX)   // 2097152 per (b,c) volume
#define ZSTR  (NY*NX)      // 16384
#define TY    16           // y-rows per block tile

#define ALPHA_F 0.001
#define MIU_F   1.0
#define EPS_F   1e-8f

// Scratch accumulators (no cudaMalloc allowed): [0]=region_in, [1]=region_out, [2]=curv
__device__ double g_acc[3];

__global__ void ace_zero_acc() {
    if (threadIdx.x < 3) g_acc[threadIdx.x] = 0.0;
}

// Block layout: blockDim = (128, 4). grid = (NY/TY, NZ, NBC).
// Each block computes a (1 z) x (TY y) x (128 x) output tile.
// Shared tile: 3 z-planes x (TY+2) y-rows x 128 x of y_pred (clamped halo).
__global__ __launch_bounds__(512)
void ace_main(const float* __restrict__ yp, const float* __restrict__ yt) {
    __shared__ float s[3][TY + 2][NX];
    __shared__ float red[3][16];

    const int bc = blockIdx.z;
    const int z  = blockIdx.y;
    const int y0 = blockIdx.x * TY;

    const float* u = yp + (size_t)bc * VOL;
    const int tid = threadIdx.y * 128 + threadIdx.x;

    // ---- cooperative load of 3 x 18 x 128 tile with clamped indices ----
    const int TOT = 3 * (TY + 2) * NX;   // 6912
    #pragma unroll 4
    for (int i = tid; i < TOT; i += 512) {
        int plane = i / ((TY + 2) * NX);
        int rem   = i - plane * ((TY + 2) * NX);
        int row   = rem >> 7;            // / 128
        int col   = rem & 127;
        int gz = z + plane - 1;
        gz = gz < 0 ? 0 : (gz > NZ - 1 ? NZ - 1 : gz);
        int gy = y0 + row - 1;
        gy = gy < 0 ? 0 : (gy > NY - 1 ? NY - 1 : gy);
        s[plane][row][col] = u[gz * ZSTR + gy * NX + col];
    }
    __syncthreads();

    const int tx = threadIdx.x;
    const int xm = tx > 0 ? tx - 1 : 0;
    const int xp = tx < NX - 1 ? tx + 1 : NX - 1;

    float acc_in = 0.f, acc_out = 0.f, acc_curv = 0.f;

    #pragma unroll
    for (int ly = threadIdx.y; ly < TY; ly += 4) {
        const int sy = ly + 1;

        const float uc  = s[1][sy][tx];
        const float uzp = s[2][sy][tx];
        const float uzm = s[0][sy][tx];
        const float uyp = s[1][sy + 1][tx];
        const float uym = s[1][sy - 1][tx];
        const float uxp = s[1][sy][xp];
        const float uxm = s[1][sy][xm];

        // first derivatives (clamped-neighbor form reproduces one-sided boundaries)
        const float ci = 0.5f * (uzp - uzm);
        const float cj = 0.5f * (uyp - uym);
        const float ck = 0.5f * (uxp - uxm);
        // second derivatives
        const float cii = uzp + uzm - 2.f * uc;
        const float cjj = uyp + uym - 2.f * uc;
        const float ckk = uxp + uxm - 2.f * uc;
        // mixed derivatives: m(c)[i] = c[clamp(i+1)] - c[clamp(i-1)]  (no /2)
        const float cij = 0.5f * ((s[2][sy + 1][tx] - s[0][sy + 1][tx])
                                - (s[2][sy - 1][tx] - s[0][sy - 1][tx]));
        const float cik = 0.5f * ((s[2][sy][xp] - s[0][sy][xp])
                                - (s[2][sy][xm] - s[0][sy][xm]));
        const float cjk = 0.5f * ((s[1][sy + 1][xp] - s[1][sy - 1][xp])
                                - (s[1][sy + 1][xm] - s[1][sy - 1][xm]));

        const float ci2 = ci * ci, cj2 = cj * cj, ck2 = ck * ck;
        const float sum2 = ci2 + cj2 + ck2;
        const float length = sqrtf(EPS_F + sum2);
        float curvature = (1.f + ci2 + cj2) * ckk
                        + (1.f + cj2 + ck2) * cii
                        + (1.f + ci2 + ck2) * cjj
                        - 2.f * cik * cjk * cij;
        const float denom = sqrtf(1.f + sum2) + EPS_F;
        const float curv = fabsf(curvature) / denom;
        acc_curv += curv * curv * fabsf(length);

        // region term (needs y_true only at the center voxel)
        const float t = yt[(size_t)bc * VOL + z * ZSTR + (y0 + ly) * NX + tx];
        const float tm1 = t - 1.f;
        acc_in  += uc * tm1 * tm1;
        acc_out += (1.f - uc) * t * t;
    }

    // ---- block reduction: warp shuffle, then cross-warp via shared ----
    #pragma unroll
    for (int off = 16; off; off >>= 1) {
        acc_in   += __shfl_down_sync(0xffffffffu, acc_in,   off);
        acc_out  += __shfl_down_sync(0xffffffffu, acc_out,  off);
        acc_curv += __shfl_down_sync(0xffffffffu, acc_curv, off);
    }
    const int wid  = tid >> 5;
    const int lane = tid & 31;
    if (lane == 0) {
        red[0][wid] = acc_in;
        red[1][wid] = acc_out;
        red[2][wid] = acc_curv;
    }
    __syncthreads();
    if (wid == 0) {
        float a = (lane < 16) ? red[0][lane] : 0.f;
        float b = (lane < 16) ? red[1][lane] : 0.f;
        float c = (lane < 16) ? red[2][lane] : 0.f;
        #pragma unroll
        for (int off = 8; off; off >>= 1) {
            a += __shfl_down_sync(0xffffffffu, a, off);
            b += __shfl_down_sync(0xffffffffu, b, off);
            c += __shfl_down_sync(0xffffffffu, c, off);
        }
        if (lane == 0) {
            atomicAdd(&g_acc[0], (double)a);
            atomicAdd(&g_acc[1], (double)b);
            atomicAdd(&g_acc[2], (double)c);
        }
    }
}

__global__ void ace_finalize(float* __restrict__ out) {
    const double region = MIU_F * fabs(g_acc[0]) + fabs(g_acc[1]);
    const double elastica = (double)NBC * (double)VOL * ALPHA_F + g_acc[2];
    out[0] = (float)(region + elastica);
}

extern "C" void kernel_launch(void* const* d_in, const int* in_sizes, int n_in,
                              void* d_out, int out_size) {
    const float* y_pred = (const float*)d_in[0];
    const float* y_true = (const float*)d_in[1];
    float* out = (float*)d_out;

    ace_zero_acc<<<1, 32>>>();
    dim3 grid(NY / TY, NZ, NBC);   // (8, 128, 6) = 6144 blocks
    dim3 block(128, 4);            // 512 threads
    ace_main<<<grid, block>>>(y_pred, y_true);
    ace_finalize<<<1, 1>>>(out);
}

// round 9
// speedup vs baseline: 1.4261x; 1.4261x over previous
#include <cuda_runtime.h>

// Problem constants
#define NBC    6            // batch*channel = 2*3
#define NZ     128
#define NY     128
#define NX     128
#define VOL    (NZ*NY*NX)   // 2097152 per (b,c) volume
#define ZSTR   (NY*NX)      // 16384
#define TY     16           // y-rows per block tile
#define ZCHUNK 16           // z-planes marched per block

#define ALPHA_F 0.001
#define MIU_F   1.0
#define EPS_F   1e-8f

// Scratch accumulators (no cudaMalloc allowed): [0]=region_in, [1]=region_out, [2]=curv
__device__ double g_acc[3];

__global__ void ace_zero_acc() {
    if (threadIdx.x < 3) g_acc[threadIdx.x] = 0.0;
}

__device__ __forceinline__ int clampi(int v, int lo, int hi) {
    return v < lo ? lo : (v > hi ? hi : v);
}

// grid = (NY/TY=8, NZ/ZCHUNK=8, NBC=6) = 384 blocks, blockDim (128,4) = 512 thr.
// Each block computes a (ZCHUNK z) x (TY y) x (128 x) tile, marching in z with
// a 4-slot ring buffer of (TY+2) x 128 y_pred planes in shared memory.
__global__ __launch_bounds__(512)
void ace_main(const float* __restrict__ yp, const float* __restrict__ yt) {
    __shared__ float s[4][TY + 2][NX];   // 36.9 KB ring buffer
    __shared__ float red[3][16];

    const int bc = blockIdx.z;
    const int z0 = blockIdx.y * ZCHUNK;
    const int y0 = blockIdx.x * TY;

    const float* u = yp + (size_t)bc * VOL;
    const int tid = threadIdx.y * 128 + threadIdx.x;
    const int tx  = threadIdx.x;

    // ---- plane loader: (TY+2) x 128 with clamped y (and clamped z by caller) ----
    auto load_plane = [&](int slot, int gz) {
        gz = clampi(gz, 0, NZ - 1);
        const float* __restrict__ src = u + gz * ZSTR;
        #pragma unroll
        for (int i = tid; i < (TY + 2) * NX; i += 512) {
            const int row = i >> 7;
            const int col = i & 127;
            const int gy  = clampi(y0 + row - 1, 0, NY - 1);
            s[slot][row][col] = src[gy * NX + col];
        }
    };

    // prologue: planes z0-1, z0, z0+1 into slots 3, 0, 1 (z0 is a multiple of 4)
    load_plane(3, z0 - 1);
    load_plane(0, z0);
    load_plane(1, z0 + 1);

    const int xm = tx > 0 ? tx - 1 : 0;
    const int xp = tx < NX - 1 ? tx + 1 : NX - 1;

    float acc_in = 0.f, acc_out = 0.f, acc_curv = 0.f;
    const float* __restrict__ ytb = yt + (size_t)bc * VOL + z0 * ZSTR + y0 * NX + tx;

    #pragma unroll 4
    for (int zz = 0; zz < ZCHUNK; zz++) {
        __syncthreads();
        // prefetch plane z+2 into the slot not read this iteration
        if (zz != ZCHUNK - 1) load_plane((zz + 2) & 3, z0 + zz + 2);

        const int sm_ = (zz + 3) & 3;   // z-1
        const int sc  =  zz      & 3;   // z
        const int sp  = (zz + 1) & 3;   // z+1

        #pragma unroll
        for (int ly = threadIdx.y; ly < TY; ly += 4) {
            const int sy = ly + 1;

            const float uc  = s[sc ][sy][tx];
            const float uzp = s[sp ][sy][tx];
            const float uzm = s[sm_][sy][tx];
            const float uyp = s[sc ][sy + 1][tx];
            const float uym = s[sc ][sy - 1][tx];
            const float uxp = s[sc ][sy][xp];
            const float uxm = s[sc ][sy][xm];

            // first derivatives (clamped-neighbor form == one-sided boundaries)
            const float ci = 0.5f * (uzp - uzm);
            const float cj = 0.5f * (uyp - uym);
            const float ck = 0.5f * (uxp - uxm);
            // second derivatives
            const float cii = uzp + uzm - 2.f * uc;
            const float cjj = uyp + uym - 2.f * uc;
            const float ckk = uxp + uxm - 2.f * uc;
            // mixed derivatives: m(c)[i] = c[clamp(i+1)] - c[clamp(i-1)]
            const float cij = 0.5f * ((s[sp ][sy + 1][tx] - s[sm_][sy + 1][tx])
                                    - (s[sp ][sy - 1][tx] - s[sm_][sy - 1][tx]));
            const float cik = 0.5f * ((s[sp ][sy][xp] - s[sm_][sy][xp])
                                    - (s[sp ][sy][xm] - s[sm_][sy][xm]));
            const float cjk = 0.5f * ((s[sc ][sy + 1][xp] - s[sc ][sy - 1][xp])
                                    - (s[sc ][sy + 1][xm] - s[sc ][sy - 1][xm]));

            const float ci2 = ci * ci, cj2 = cj * cj, ck2 = ck * ck;
            const float s2  = ci2 + cj2 + ck2;
            const float len = sqrtf(EPS_F + s2);
            const float curvature = (1.f + ci2 + cj2) * ckk
                                  + (1.f + cj2 + ck2) * cii
                                  + (1.f + ci2 + ck2) * cjj
                                  - 2.f * cik * cjk * cij;
            // curv^2*|len| with curv = |K|/(sqrt(1+s2)+EPS); (sqrt(1+s2)+EPS)^2 ~= 1+s2
            const float q = fabsf(curvature);
            acc_curv += __fdividef(q * q * len, 1.f + s2);

            // region term (y_true only at center voxel; coalesced global load)
            const float t = ytb[zz * ZSTR + ly * NX];
            const float tm1 = t - 1.f;
            acc_in  += uc * tm1 * tm1;
            acc_out += (1.f - uc) * t * t;
        }
    }

    // ---- block reduction: warp shuffle, then cross-warp via shared ----
    #pragma unroll
    for (int off = 16; off; off >>= 1) {
        acc_in   += __shfl_down_sync(0xffffffffu, acc_in,   off);
        acc_out  += __shfl_down_sync(0xffffffffu, acc_out,  off);
        acc_curv += __shfl_down_sync(0xffffffffu, acc_curv, off);
    }
    const int wid  = tid >> 5;
    const int lane = tid & 31;
    if (lane == 0) {
        red[0][wid] = acc_in;
        red[1][wid] = acc_out;
        red[2][wid] = acc_curv;
    }
    __syncthreads();
    if (wid == 0) {
        float a = (lane < 16) ? red[0][lane] : 0.f;
        float b = (lane < 16) ? red[1][lane] : 0.f;
        float c = (lane < 16) ? red[2][lane] : 0.f;
        #pragma unroll
        for (int off = 8; off; off >>= 1) {
            a += __shfl_down_sync(0xffffffffu, a, off);
            b += __shfl_down_sync(0xffffffffu, b, off);
            c += __shfl_down_sync(0xffffffffu, c, off);
        }
        if (lane == 0) {
            atomicAdd(&g_acc[0], (double)a);
            atomicAdd(&g_acc[1], (double)b);
            atomicAdd(&g_acc[2], (double)c);
        }
    }
}

__global__ void ace_finalize(float* __restrict__ out) {
    const double region = MIU_F * fabs(g_acc[0]) + fabs(g_acc[1]);
    const double elastica = (double)NBC * (double)VOL * ALPHA_F + g_acc[2];
    out[0] = (float)(region + elastica);
}

extern "C" void kernel_launch(void* const* d_in, const int* in_sizes, int n_in,
                              void* d_out, int out_size) {
    const float* y_pred = (const float*)d_in[0];
    const float* y_true = (const float*)d_in[1];
    float* out = (float*)d_out;

    ace_zero_acc<<<1, 32>>>();
    dim3 grid(NY / TY, NZ / ZCHUNK, NBC);   // (8, 8, 6) = 384 blocks
    dim3 block(128, 4);                     // 512 threads
    ace_main<<<grid, block>>>(y_pred, y_true);
    ace_finalize<<<1, 1>>>(out);
}